// round 8
// baseline (speedup 1.0000x reference)
#include <cuda_runtime.h>
#include <math.h>
#include <stdint.h>

// Problem dims (fixed)
#define NT 2048
#define NB 64
#define NI 256
#define NH 512
#define NG 2048
#define GRID_B 128   // 32 unit-groups x 4 batch-groups, 1 CTA/SM, single wave
#define HP 36        // shD row pitch (floats): 32 dup floats + 4 pad (bank stagger)

// Scratch (__device__ globals; no allocation allowed)
__device__ float g_xw[(size_t)NT * NG * NB];   // [t][col][b]
__device__ float g_h[2 * NH * NB];             // [buf][k][b]
__device__ unsigned g_flag[4 * 32 * 32];       // flag[(bgp*32+slice)*32] = step avail

__device__ __forceinline__ float fast_sigmoid(float x) {
    return __fdividef(1.0f, 1.0f + __expf(-x));
}
__device__ __forceinline__ float fast_tanh(float x) {
    float t = __expf(2.0f * x);
    return 1.0f - __fdividef(2.0f, t + 1.0f);
}

// ---- packed f32x2 helpers ----
__device__ __forceinline__ unsigned long long fma2(unsigned long long a,
                                                   unsigned long long b,
                                                   unsigned long long c) {
    unsigned long long d;
    asm("fma.rn.f32x2 %0, %1, %2, %3;" : "=l"(d) : "l"(a), "l"(b), "l"(c));
    return d;
}
__device__ __forceinline__ unsigned long long pack2(float x, float y) {
    unsigned long long r;
    asm("mov.b64 %0, {%1, %2};" : "=l"(r) : "f"(x), "f"(y));
    return r;
}
__device__ __forceinline__ float2 unpack2(unsigned long long v) {
    float2 f;
    asm("mov.b64 {%0, %1}, %2;" : "=f"(f.x), "=f"(f.y) : "l"(v));
    return f;
}
__device__ __forceinline__ unsigned ld_acquire(const unsigned* p) {
    unsigned v;
    asm volatile("ld.acquire.gpu.global.b32 %0, [%1];" : "=r"(v) : "l"(p));
    return v;
}
__device__ __forceinline__ void cp16(float* smem_dst, const float* gsrc) {
    unsigned d = (unsigned)__cvta_generic_to_shared(smem_dst);
    asm volatile("cp.async.ca.shared.global [%0], [%1], 16;" :: "r"(d), "l"(gsrc));
}

// Prelude: zero h buffer 0 and all flags (every launch/replay).
__global__ void init_kernel() {
    int i = blockIdx.x * blockDim.x + threadIdx.x;
    if (i < NH * NB) g_h[i] = 0.f;
    if (i < 4 * 32 * 32) g_flag[i] = 0u;
}

// ---------------- Phase 1: xW = x @ Wi + B, output TRANSPOSED [t][col][b] ----
__global__ void __launch_bounds__(256, 2)
xw_gemm_kernel(const float* __restrict__ x, const float* __restrict__ Wi,
               const float* __restrict__ bias) {
    __shared__ __align__(16) float As[2][8][132];
    __shared__ __align__(16) float Bs[3][8][128];

    const int tid = threadIdx.x;
    const int tx = tid & 15, ty = tid >> 4;
    const int bm = blockIdx.y << 7, bn = blockIdx.x << 7;
    const int lrow = tid >> 1, lk = (tid & 1) << 2;
    const int brow = tid >> 5, bcol = (tid & 31) << 2;

    unsigned long long acc2[8][4];
    #pragma unroll
    for (int i = 0; i < 8; i++)
        #pragma unroll
        for (int j = 0; j < 4; j++) acc2[i][j] = 0ull;

    const float* xrow = x + (size_t)(bm + lrow) * NI + lk;
    float4 av = *reinterpret_cast<const float4*>(xrow);
    cp16(&Bs[0][brow][bcol], Wi + (size_t)brow * NG + bn + bcol);
    asm volatile("cp.async.commit_group;");

    for (int i = 0; i < 32; i++) {
        const int cur = i & 1;
        As[cur][lk + 0][lrow] = av.x;
        As[cur][lk + 1][lrow] = av.y;
        As[cur][lk + 2][lrow] = av.z;
        As[cur][lk + 3][lrow] = av.w;
        if (i < 31) {
            av = *reinterpret_cast<const float4*>(xrow + (i + 1) * 8);
            cp16(&Bs[(i + 1) % 3][brow][bcol],
                 Wi + (size_t)((i + 1) * 8 + brow) * NG + bn + bcol);
            asm volatile("cp.async.commit_group;");
            asm volatile("cp.async.wait_group 1;");
        } else {
            asm volatile("cp.async.wait_group 0;");
        }
        __syncthreads();

        const float (*Ac)[132] = As[cur];
        const float (*Bc)[128] = Bs[i % 3];
        #pragma unroll
        for (int kk = 0; kk < 8; kk++) {
            float4 t0 = *reinterpret_cast<const float4*>(&Ac[kk][ty << 3]);
            float4 t1 = *reinterpret_cast<const float4*>(&Ac[kk][(ty << 3) + 4]);
            const ulonglong2* brow2 = reinterpret_cast<const ulonglong2*>(&Bc[kk][tx << 3]);
            ulonglong2 bv0 = brow2[0], bv1 = brow2[1];
            unsigned long long b2[4] = {bv0.x, bv0.y, bv1.x, bv1.y};
            float a[8] = {t0.x, t0.y, t0.z, t0.w, t1.x, t1.y, t1.z, t1.w};
            #pragma unroll
            for (int ii = 0; ii < 8; ii++) {
                unsigned long long ap = pack2(a[ii], a[ii]);
                #pragma unroll
                for (int j = 0; j < 4; j++)
                    acc2[ii][j] = fma2(ap, b2[j], acc2[ii][j]);
            }
        }
    }

    float4 bb0 = *reinterpret_cast<const float4*>(bias + bn + (tx << 3));
    float4 bb1 = *reinterpret_cast<const float4*>(bias + bn + (tx << 3) + 4);
    const float bb[8] = {bb0.x, bb0.y, bb0.z, bb0.w, bb1.x, bb1.y, bb1.z, bb1.w};

    const int t_idx = (bm >> 6) + (ty >> 3);
    const int b_base = (ty & 7) << 3;
    float o[8][8];
    #pragma unroll
    for (int i = 0; i < 8; i++)
        #pragma unroll
        for (int p = 0; p < 4; p++) {
            float2 v = unpack2(acc2[i][p]);
            o[i][2 * p] = v.x + bb[2 * p];
            o[i][2 * p + 1] = v.y + bb[2 * p + 1];
        }
    #pragma unroll
    for (int j = 0; j < 8; j++) {
        int col = bn + (tx << 3) + j;
        float* dst = g_xw + ((size_t)t_idx * NG + col) * NB + b_base;
        *reinterpret_cast<float4*>(dst)     = make_float4(o[0][j], o[1][j], o[2][j], o[3][j]);
        *reinterpret_cast<float4*>(dst + 4) = make_float4(o[4][j], o[5][j], o[6][j], o[7][j]);
    }
}

// ---------------- Phase 2: persistent recurrence ----------------
// CTA (ug, bgp): units 16ug..+15 (all 4 gates = 64 cols), batches 16bgp..+15.
// 16 warps; warp w owns k rows [32w, 32w+32). Flow per step:
//   wait own flag (partials of t-1 consumed) + 2 slice flags; stage DUPLICATED
//   h into shD[row][HP] (ready (b,b) FFMA2 pairs, zero movs); matmul (pure
//   FFMA2); write partials into OWN shD region (alias, warp-local safe);
//   syncthreads; 256 cell threads: direct reduce + cell + h store + bar9 +
//   flag publish; out stores after publish.
// SMEM: sWh [512][64] perm 128KB | shD [512][HP] 72KB (sRed alias) = 200KB.
#define SMEM2_FLOATS (NH * 64 + NH * HP)

__global__ void __launch_bounds__(512, 1)
lstm_rec_kernel(const float* __restrict__ Wh, float* __restrict__ out, int write_state) {
    extern __shared__ float smem[];
    float* sWh = smem;                  // [k][64] permuted: wA chunks | wB chunks
    float* shD = sWh + NH * 64;         // [k][HP] dup h; warp w region = sRed[w]

    const int tid = threadIdx.x;
    const int wid = tid >> 5;
    const int lane = tid & 31;
    const int ug = blockIdx.x >> 2;
    const int bgp = blockIdx.x & 3;

    // Wh fill, permuted row: phys = half*32 + cg*4 + i4 <-> logical col cg*8+half*4+i4.
    for (int idx = tid; idx < NH * 64; idx += 512) {
        int k = idx >> 6, ph = idx & 63;
        int half = ph >> 5, rem = ph & 31, cgf = rem >> 2, i4 = rem & 3;
        int c = cgf * 8 + half * 4 + i4;
        int gcol = ((c >> 4) << 9) + (ug << 4) + (c & 15);
        sWh[idx] = Wh[(size_t)k * NG + gcol];
    }
    __syncthreads();

    const int cg = lane >> 2, bq = lane & 3;
    const int g_of = cg >> 1, u8 = (cg & 1) << 3;
    const int srl = lane >> 2, spart = lane & 3;   // staging: row-in-8, batch-quad

    const unsigned* fl0 = &g_flag[(bgp * 32 + 2 * wid) * 32];
    const unsigned* fl1 = &g_flag[(bgp * 32 + 2 * wid + 1) * 32];
    const unsigned* flown = &g_flag[(bgp * 32 + ug) * 32];

    const float* wbase = sWh + (wid << 5) * 64 + (cg << 2);
    const float* hbase = shD + (wid << 5) * HP + (bq << 3);
    float* sred_w = shD + wid * (32 * HP) + (g_of << 8) + u8;   // + b*16

    const int u_ = tid & 15, b2 = tid >> 4;        // cell mapping (tid<256)
    const int hrow = (ug << 4) + u_;
    const int bglob = (bgp << 4) + b2;
    float c_reg = 0.f;

    for (int t = 0; t < NT; t++) {
        // Prefetch xW (cell threads; in flight through waits + matmul).
        float xw0 = 0.f, xw1 = 0.f, xw2 = 0.f, xw3 = 0.f;
        if (tid < 256) {
            const float* xwt = g_xw + (size_t)t * ((size_t)NG * NB) + (size_t)hrow * NB + bglob;
            xw0 = __ldg(xwt);
            xw1 = __ldg(xwt + (size_t)(1 << 9) * NB);
            xw2 = __ldg(xwt + (size_t)(2 << 9) * NB);
            xw3 = __ldg(xwt + (size_t)(3 << 9) * NB);
        }

        // Own flag >= t: this CTA's cell consumed warp-region partials of t-1.
        while (ld_acquire(flown) < (unsigned)t) { __nanosleep(20); }

        // Stage 32 rows (2 slices) with duplication: shD[r][2b]=shD[r][2b+1]=h[r][b].
        const float* src = g_h + (t & 1) * (NH * NB) + (bgp << 4) + (spart << 2);
        while (ld_acquire(fl0) < (unsigned)t) { __nanosleep(20); }
        #pragma unroll
        for (int i = 0; i < 2; i++) {
            int row = (wid << 5) + (i << 3) + srl;
            float4 v = __ldcg(reinterpret_cast<const float4*>(src + row * NB));
            float* d = shD + row * HP + (spart << 3);
            *reinterpret_cast<float4*>(d)     = make_float4(v.x, v.x, v.y, v.y);
            *reinterpret_cast<float4*>(d + 4) = make_float4(v.z, v.z, v.w, v.w);
        }
        while (ld_acquire(fl1) < (unsigned)t) { __nanosleep(20); }
        #pragma unroll
        for (int i = 2; i < 4; i++) {
            int row = (wid << 5) + (i << 3) + srl;
            float4 v = __ldcg(reinterpret_cast<const float4*>(src + row * NB));
            float* d = shD + row * HP + (spart << 3);
            *reinterpret_cast<float4*>(d)     = make_float4(v.x, v.x, v.y, v.y);
            *reinterpret_cast<float4*>(d + 4) = make_float4(v.z, v.z, v.w, v.w);
        }
        __syncwarp();

        // Matmul over 32 k rows: 4 col-pairs x 4 batches, pure FFMA2 (no movs).
        unsigned long long acc[4][4];
        #pragma unroll
        for (int cp = 0; cp < 4; cp++)
            #pragma unroll
            for (int j = 0; j < 4; j++) acc[cp][j] = 0ull;

        const float* wp_ = wbase;
        const float* hp_ = hbase;
        #pragma unroll 8
        for (int kl = 0; kl < 32; kl++) {
            ulonglong2 wA = *reinterpret_cast<const ulonglong2*>(wp_);
            ulonglong2 wB = *reinterpret_cast<const ulonglong2*>(wp_ + 32);
            ulonglong2 hA = *reinterpret_cast<const ulonglong2*>(hp_);
            ulonglong2 hB = *reinterpret_cast<const ulonglong2*>(hp_ + 4);
            unsigned long long wq[4] = {wA.x, wA.y, wB.x, wB.y};
            unsigned long long hd[4] = {hA.x, hA.y, hB.x, hB.y};
            #pragma unroll
            for (int cp = 0; cp < 4; cp++) {
                acc[cp][0] = fma2(wq[cp], hd[0], acc[cp][0]);
                acc[cp][1] = fma2(wq[cp], hd[1], acc[cp][1]);
                acc[cp][2] = fma2(wq[cp], hd[2], acc[cp][2]);
                acc[cp][3] = fma2(wq[cp], hd[3], acc[cp][3]);
            }
            wp_ += 64;
            hp_ += HP;
        }

        // Partials into OWN region (only this warp read these rows): [g][b16][u16].
        #pragma unroll
        for (int j = 0; j < 4; j++) {
            float2 p0 = unpack2(acc[0][j]);
            float2 p1 = unpack2(acc[1][j]);
            float2 p2 = unpack2(acc[2][j]);
            float2 p3 = unpack2(acc[3][j]);
            float* dst = sred_w + (((bq << 2) + j) << 4);
            *reinterpret_cast<float4*>(dst)     = make_float4(p0.x, p0.y, p1.x, p1.y);
            *reinterpret_cast<float4*>(dst + 4) = make_float4(p2.x, p2.y, p3.x, p3.y);
        }
        __syncthreads();   // all partials visible to cell threads

        // Cell: direct 16-warp reduce + activations + h store (tid < 256).
        if (tid < 256) {
            float G0 = xw0, G1 = xw1, G2 = xw2, G3 = xw3;
            const float* rp = shD + (b2 << 4) + u_;
            #pragma unroll
            for (int w = 0; w < 16; w++) {
                G0 += rp[0];
                G1 += rp[256];
                G2 += rp[512];
                G3 += rp[768];
                rp += 32 * HP;
            }
            float ig = fast_sigmoid(G0);
            float fg = fast_sigmoid(G1);
            float gg = fast_tanh(G2);
            float og = fast_sigmoid(G3);
            c_reg = fg * c_reg + ig * gg;
            float h = og * fast_tanh(c_reg);

            __stcg(&g_h[((t + 1) & 1) * (NH * NB) + hrow * NB + bglob], h);
            asm volatile("bar.sync 9, 256;");   // all cell h-stores issued & reads done
            if (tid == 0) {
                __threadfence();
                asm volatile("st.release.gpu.global.b32 [%0], %1;"
                             :: "l"(flown), "r"((unsigned)(t + 1)) : "memory");
            }
            // Off the critical path:
            out[((size_t)t * NB + bglob) * NH + hrow] = h;
            if (write_state && t == NT - 1) {
                size_t base = (size_t)NT * NB * NH;
                out[base + (size_t)bglob * NH + hrow] = h;
                out[base + (size_t)NB * NH + (size_t)bglob * NH + hrow] = c_reg;
            }
        }
    }
}

extern "C" void kernel_launch(void* const* d_in, const int* in_sizes, int n_in,
                              void* d_out, int out_size) {
    const float* x  = (const float*)d_in[0];
    const float* Wi = (const float*)d_in[1];
    const float* Wh = (const float*)d_in[2];
    const float* B  = (const float*)d_in[3];
    float* out = (float*)d_out;

    const int smem_bytes = SMEM2_FLOATS * (int)sizeof(float);   // 204800 B
    cudaFuncSetAttribute(lstm_rec_kernel, cudaFuncAttributeMaxDynamicSharedMemorySize, smem_bytes);

    init_kernel<<<32, 1024>>>();   // zero h0 + flags (every launch/replay)

    dim3 gA(NG / 128, (NT * NB) / 128);
    xw_gemm_kernel<<<gA, 256>>>(x, Wi, B);

    const long long need_full = (long long)NT * NB * NH + 2LL * NB * NH;
    int write_state = ((long long)out_size >= need_full) ? 1 : 0;

    lstm_rec_kernel<<<GRID_B, 512, smem_bytes>>>(Wh, out, write_state);
}

// round 9
// speedup vs baseline: 1.0433x; 1.0433x over previous
#include <cuda_runtime.h>
#include <math.h>
#include <stdint.h>

// Problem dims (fixed)
#define NT 2048
#define NB 64
#define NI 256
#define NH 512
#define NG 2048
#define GRID_B 128   // 32 unit-groups x 4 batch-groups, 1 CTA/SM, single wave
#define HP 36        // shD row pitch (floats): 32 dup floats + 4 pad (bank stagger)

// Scratch (__device__ globals; no allocation allowed)
__device__ float g_xw[(size_t)NT * NG * NB];   // [t][col][b]
__device__ float g_h[2 * NH * NB];             // [buf][k][b]
__device__ unsigned g_flag[4 * 32 * 32];       // flag[(bgp*32+ug)*32] = step avail

__device__ __forceinline__ float fast_sigmoid(float x) {
    return __fdividef(1.0f, 1.0f + __expf(-x));
}
__device__ __forceinline__ float fast_tanh(float x) {
    float t = __expf(2.0f * x);
    return 1.0f - __fdividef(2.0f, t + 1.0f);
}

// ---- packed f32x2 helpers ----
__device__ __forceinline__ unsigned long long fma2(unsigned long long a,
                                                   unsigned long long b,
                                                   unsigned long long c) {
    unsigned long long d;
    asm("fma.rn.f32x2 %0, %1, %2, %3;" : "=l"(d) : "l"(a), "l"(b), "l"(c));
    return d;
}
__device__ __forceinline__ unsigned long long pack2(float x, float y) {
    unsigned long long r;
    asm("mov.b64 %0, {%1, %2};" : "=l"(r) : "f"(x), "f"(y));
    return r;
}
__device__ __forceinline__ float2 unpack2(unsigned long long v) {
    float2 f;
    asm("mov.b64 {%0, %1}, %2;" : "=f"(f.x), "=f"(f.y) : "l"(v));
    return f;
}
__device__ __forceinline__ unsigned ld_acquire(const unsigned* p) {
    unsigned v;
    asm volatile("ld.acquire.gpu.global.b32 %0, [%1];" : "=r"(v) : "l"(p));
    return v;
}
__device__ __forceinline__ void cp16(float* smem_dst, const float* gsrc) {
    unsigned d = (unsigned)__cvta_generic_to_shared(smem_dst);
    asm volatile("cp.async.ca.shared.global [%0], [%1], 16;" :: "r"(d), "l"(gsrc));
}

// Prelude: zero h buffer 0 and all flags (every launch/replay).
__global__ void init_kernel() {
    int i = blockIdx.x * blockDim.x + threadIdx.x;
    if (i < NH * NB) g_h[i] = 0.f;
    if (i < 4 * 32 * 32) g_flag[i] = 0u;
}

// ---------------- Phase 1: xW = x @ Wi + B, output TRANSPOSED [t][col][b] ----
__global__ void __launch_bounds__(256, 2)
xw_gemm_kernel(const float* __restrict__ x, const float* __restrict__ Wi,
               const float* __restrict__ bias) {
    __shared__ __align__(16) float As[2][8][132];
    __shared__ __align__(16) float Bs[3][8][128];

    const int tid = threadIdx.x;
    const int tx = tid & 15, ty = tid >> 4;
    const int bm = blockIdx.y << 7, bn = blockIdx.x << 7;
    const int lrow = tid >> 1, lk = (tid & 1) << 2;
    const int brow = tid >> 5, bcol = (tid & 31) << 2;

    unsigned long long acc2[8][4];
    #pragma unroll
    for (int i = 0; i < 8; i++)
        #pragma unroll
        for (int j = 0; j < 4; j++) acc2[i][j] = 0ull;

    const float* xrow = x + (size_t)(bm + lrow) * NI + lk;
    float4 av = *reinterpret_cast<const float4*>(xrow);
    cp16(&Bs[0][brow][bcol], Wi + (size_t)brow * NG + bn + bcol);
    asm volatile("cp.async.commit_group;");

    for (int i = 0; i < 32; i++) {
        const int cur = i & 1;
        As[cur][lk + 0][lrow] = av.x;
        As[cur][lk + 1][lrow] = av.y;
        As[cur][lk + 2][lrow] = av.z;
        As[cur][lk + 3][lrow] = av.w;
        if (i < 31) {
            av = *reinterpret_cast<const float4*>(xrow + (i + 1) * 8);
            cp16(&Bs[(i + 1) % 3][brow][bcol],
                 Wi + (size_t)((i + 1) * 8 + brow) * NG + bn + bcol);
            asm volatile("cp.async.commit_group;");
            asm volatile("cp.async.wait_group 1;");
        } else {
            asm volatile("cp.async.wait_group 0;");
        }
        __syncthreads();

        const float (*Ac)[132] = As[cur];
        const float (*Bc)[128] = Bs[i % 3];
        #pragma unroll
        for (int kk = 0; kk < 8; kk++) {
            float4 t0 = *reinterpret_cast<const float4*>(&Ac[kk][ty << 3]);
            float4 t1 = *reinterpret_cast<const float4*>(&Ac[kk][(ty << 3) + 4]);
            const ulonglong2* brow2 = reinterpret_cast<const ulonglong2*>(&Bc[kk][tx << 3]);
            ulonglong2 bv0 = brow2[0], bv1 = brow2[1];
            unsigned long long b2[4] = {bv0.x, bv0.y, bv1.x, bv1.y};
            float a[8] = {t0.x, t0.y, t0.z, t0.w, t1.x, t1.y, t1.z, t1.w};
            #pragma unroll
            for (int ii = 0; ii < 8; ii++) {
                unsigned long long ap = pack2(a[ii], a[ii]);
                #pragma unroll
                for (int j = 0; j < 4; j++)
                    acc2[ii][j] = fma2(ap, b2[j], acc2[ii][j]);
            }
        }
    }

    float4 bb0 = *reinterpret_cast<const float4*>(bias + bn + (tx << 3));
    float4 bb1 = *reinterpret_cast<const float4*>(bias + bn + (tx << 3) + 4);
    const float bb[8] = {bb0.x, bb0.y, bb0.z, bb0.w, bb1.x, bb1.y, bb1.z, bb1.w};

    const int t_idx = (bm >> 6) + (ty >> 3);
    const int b_base = (ty & 7) << 3;
    float o[8][8];
    #pragma unroll
    for (int i = 0; i < 8; i++)
        #pragma unroll
        for (int p = 0; p < 4; p++) {
            float2 v = unpack2(acc2[i][p]);
            o[i][2 * p] = v.x + bb[2 * p];
            o[i][2 * p + 1] = v.y + bb[2 * p + 1];
        }
    #pragma unroll
    for (int j = 0; j < 8; j++) {
        int col = bn + (tx << 3) + j;
        float* dst = g_xw + ((size_t)t_idx * NG + col) * NB + b_base;
        *reinterpret_cast<float4*>(dst)     = make_float4(o[0][j], o[1][j], o[2][j], o[3][j]);
        *reinterpret_cast<float4*>(dst + 4) = make_float4(o[4][j], o[5][j], o[6][j], o[7][j]);
    }
}

// ---------------- Phase 2: persistent recurrence ----------------
// CTA (ug, bgp): units 16ug..+15 (all 4 gates = 64 cols), batches 16bgp..+15.
// 16 warps; warp w owns k rows [32w, 32w+32). Per step:
//   wait 2 slice flags >= t; stage DUPLICATED h into shD[row][HP] (ready (b,b)
//   FFMA2 pairs, zero movs in matmul); matmul (pure FFMA2); partials into OWN
//   shD region (warp-local alias, safe); syncthreads; 256 cell threads: direct
//   reduce + cell + h store + bar9 + flag publish; out stores after publish;
//   loop-end syncthreads orders partial reads before next staging (intra-CTA,
//   cheap — this replaces R8's costly global own-flag wait).
// SMEM: sWh [512][64] perm 128KB | shD [512][HP] 72KB (sRed alias) = 200KB.
#define SMEM2_FLOATS (NH * 64 + NH * HP)

__global__ void __launch_bounds__(512, 1)
lstm_rec_kernel(const float* __restrict__ Wh, float* __restrict__ out, int write_state) {
    extern __shared__ float smem[];
    float* sWh = smem;                  // [k][64] permuted: wA chunks | wB chunks
    float* shD = sWh + NH * 64;         // [k][HP] dup h; warp w region = sRed[w]

    const int tid = threadIdx.x;
    const int wid = tid >> 5;
    const int lane = tid & 31;
    const int ug = blockIdx.x >> 2;
    const int bgp = blockIdx.x & 3;

    // Wh fill, permuted row: phys = half*32 + cg*4 + i4 <-> logical col cg*8+half*4+i4.
    for (int idx = tid; idx < NH * 64; idx += 512) {
        int k = idx >> 6, ph = idx & 63;
        int half = ph >> 5, rem = ph & 31, cgf = rem >> 2, i4 = rem & 3;
        int c = cgf * 8 + half * 4 + i4;
        int gcol = ((c >> 4) << 9) + (ug << 4) + (c & 15);
        sWh[idx] = Wh[(size_t)k * NG + gcol];
    }
    __syncthreads();

    const int cg = lane >> 2, bq = lane & 3;
    const int g_of = cg >> 1, u8 = (cg & 1) << 3;
    const int srl = lane >> 2, spart = lane & 3;   // staging: row-in-8, batch-quad

    const unsigned* fl0 = &g_flag[(bgp * 32 + 2 * wid) * 32];
    const unsigned* fl1 = &g_flag[(bgp * 32 + 2 * wid + 1) * 32];
    const unsigned* flown = &g_flag[(bgp * 32 + ug) * 32];

    const float* wbase = sWh + (wid << 5) * 64 + (cg << 2);
    const float* hbase = shD + (wid << 5) * HP + (bq << 3);
    float* sred_w = shD + wid * (32 * HP) + (g_of << 8) + u8;   // + b*16

    const int u_ = tid & 15, b2 = tid >> 4;        // cell mapping (tid<256)
    const int hrow = (ug << 4) + u_;
    const int bglob = (bgp << 4) + b2;
    float c_reg = 0.f;

    for (int t = 0; t < NT; t++) {
        // Prefetch xW (cell threads; in flight through waits + matmul).
        float xw0 = 0.f, xw1 = 0.f, xw2 = 0.f, xw3 = 0.f;
        if (tid < 256) {
            const float* xwt = g_xw + (size_t)t * ((size_t)NG * NB) + (size_t)hrow * NB + bglob;
            xw0 = __ldg(xwt);
            xw1 = __ldg(xwt + (size_t)(1 << 9) * NB);
            xw2 = __ldg(xwt + (size_t)(2 << 9) * NB);
            xw3 = __ldg(xwt + (size_t)(3 << 9) * NB);
        }

        // Stage 32 rows (2 slices) with duplication: shD[r][2b]=shD[r][2b+1]=h[r][b].
        const float* src = g_h + (t & 1) * (NH * NB) + (bgp << 4) + (spart << 2);
        while (ld_acquire(fl0) < (unsigned)t) { __nanosleep(20); }
        #pragma unroll
        for (int i = 0; i < 2; i++) {
            int row = (wid << 5) + (i << 3) + srl;
            float4 v = __ldcg(reinterpret_cast<const float4*>(src + row * NB));
            float* d = shD + row * HP + (spart << 3);
            *reinterpret_cast<float4*>(d)     = make_float4(v.x, v.x, v.y, v.y);
            *reinterpret_cast<float4*>(d + 4) = make_float4(v.z, v.z, v.w, v.w);
        }
        while (ld_acquire(fl1) < (unsigned)t) { __nanosleep(20); }
        #pragma unroll
        for (int i = 2; i < 4; i++) {
            int row = (wid << 5) + (i << 3) + srl;
            float4 v = __ldcg(reinterpret_cast<const float4*>(src + row * NB));
            float* d = shD + row * HP + (spart << 3);
            *reinterpret_cast<float4*>(d)     = make_float4(v.x, v.x, v.y, v.y);
            *reinterpret_cast<float4*>(d + 4) = make_float4(v.z, v.z, v.w, v.w);
        }
        __syncwarp();

        // Matmul over 32 k rows: 4 col-pairs x 4 batches, pure FFMA2 (no movs).
        unsigned long long acc[4][4];
        #pragma unroll
        for (int cp = 0; cp < 4; cp++)
            #pragma unroll
            for (int j = 0; j < 4; j++) acc[cp][j] = 0ull;

        const float* wp_ = wbase;
        const float* hp_ = hbase;
        #pragma unroll 8
        for (int kl = 0; kl < 32; kl++) {
            ulonglong2 wA = *reinterpret_cast<const ulonglong2*>(wp_);
            ulonglong2 wB = *reinterpret_cast<const ulonglong2*>(wp_ + 32);
            ulonglong2 hA = *reinterpret_cast<const ulonglong2*>(hp_);
            ulonglong2 hB = *reinterpret_cast<const ulonglong2*>(hp_ + 4);
            unsigned long long wq[4] = {wA.x, wA.y, wB.x, wB.y};
            unsigned long long hd[4] = {hA.x, hA.y, hB.x, hB.y};
            #pragma unroll
            for (int cp = 0; cp < 4; cp++) {
                acc[cp][0] = fma2(wq[cp], hd[0], acc[cp][0]);
                acc[cp][1] = fma2(wq[cp], hd[1], acc[cp][1]);
                acc[cp][2] = fma2(wq[cp], hd[2], acc[cp][2]);
                acc[cp][3] = fma2(wq[cp], hd[3], acc[cp][3]);
            }
            wp_ += 64;
            hp_ += HP;
        }

        // Partials into OWN region (only this warp used these rows): [g][b16][u16].
        #pragma unroll
        for (int j = 0; j < 4; j++) {
            float2 p0 = unpack2(acc[0][j]);
            float2 p1 = unpack2(acc[1][j]);
            float2 p2 = unpack2(acc[2][j]);
            float2 p3 = unpack2(acc[3][j]);
            float* dst = sred_w + (((bq << 2) + j) << 4);
            *reinterpret_cast<float4*>(dst)     = make_float4(p0.x, p0.y, p1.x, p1.y);
            *reinterpret_cast<float4*>(dst + 4) = make_float4(p2.x, p2.y, p3.x, p3.y);
        }
        __syncthreads();   // all partials visible to cell threads

        // Cell: direct 16-warp reduce + activations + h store (tid < 256).
        if (tid < 256) {
            float G0 = xw0, G1 = xw1, G2 = xw2, G3 = xw3;
            const float* rp = shD + (b2 << 4) + u_;
            #pragma unroll
            for (int w = 0; w < 16; w++) {
                G0 += rp[0];
                G1 += rp[256];
                G2 += rp[512];
                G3 += rp[768];
                rp += 32 * HP;
            }
            float ig = fast_sigmoid(G0);
            float fg = fast_sigmoid(G1);
            float gg = fast_tanh(G2);
            float og = fast_sigmoid(G3);
            c_reg = fg * c_reg + ig * gg;
            float h = og * fast_tanh(c_reg);

            __stcg(&g_h[((t + 1) & 1) * (NH * NB) + hrow * NB + bglob], h);
            asm volatile("bar.sync 9, 256;");   // all cell h-stores issued
            if (tid == 0) {
                __threadfence();
                asm volatile("st.release.gpu.global.b32 [%0], %1;"
                             :: "l"(flown), "r"((unsigned)(t + 1)) : "memory");
            }
            // Off the critical path:
            out[((size_t)t * NB + bglob) * NH + hrow] = h;
            if (write_state && t == NT - 1) {
                size_t base = (size_t)NT * NB * NH;
                out[base + (size_t)bglob * NH + hrow] = h;
                out[base + (size_t)NB * NH + (size_t)bglob * NH + hrow] = c_reg;
            }
        }
        __syncthreads();   // partial reads done before next staging (intra-CTA)
    }
}

extern "C" void kernel_launch(void* const* d_in, const int* in_sizes, int n_in,
                              void* d_out, int out_size) {
    const float* x  = (const float*)d_in[0];
    const float* Wi = (const float*)d_in[1];
    const float* Wh = (const float*)d_in[2];
    const float* B  = (const float*)d_in[3];
    float* out = (float*)d_out;

    const int smem_bytes = SMEM2_FLOATS * (int)sizeof(float);   // 204800 B
    cudaFuncSetAttribute(lstm_rec_kernel, cudaFuncAttributeMaxDynamicSharedMemorySize, smem_bytes);

    init_kernel<<<32, 1024>>>();   // zero h0 + flags (every launch/replay)

    dim3 gA(NG / 128, (NT * NB) / 128);
    xw_gemm_kernel<<<gA, 256>>>(x, Wi, B);

    const long long need_full = (long long)NT * NB * NH + 2LL * NB * NH;
    int write_state = ((long long)out_size >= need_full) ? 1 : 0;

    lstm_rec_kernel<<<GRID_B, 512, smem_bytes>>>(Wh, out, write_state);
}

// round 10
// speedup vs baseline: 1.2543x; 1.2023x over previous
#include <cuda_runtime.h>
#include <math.h>
#include <stdint.h>

// Problem dims (fixed)
#define NT 2048
#define NB 64
#define NI 256
#define NH 512
#define NG 2048
#define GRID_B 128   // 32 unit-groups x 4 batch-groups, 1 CTA/SM, single wave

// Scratch (__device__ globals; no allocation allowed)
__device__ float g_xw[(size_t)NT * NG * NB];   // [t][col][b]
__device__ float g_h[2 * NH * NB];             // [buf][k][b]
__device__ unsigned g_flag[4 * 32 * 32];       // flag[(bgp*32+slice)*32] = step avail

__device__ __forceinline__ float fast_sigmoid(float x) {
    return __fdividef(1.0f, 1.0f + __expf(-x));
}
__device__ __forceinline__ float fast_tanh(float x) {
    float t = __expf(2.0f * x);
    return 1.0f - __fdividef(2.0f, t + 1.0f);
}

// ---- packed f32x2 helpers ----
__device__ __forceinline__ unsigned long long fma2(unsigned long long a,
                                                   unsigned long long b,
                                                   unsigned long long c) {
    unsigned long long d;
    asm("fma.rn.f32x2 %0, %1, %2, %3;" : "=l"(d) : "l"(a), "l"(b), "l"(c));
    return d;
}
__device__ __forceinline__ unsigned long long pack2(float x, float y) {
    unsigned long long r;
    asm("mov.b64 %0, {%1, %2};" : "=l"(r) : "f"(x), "f"(y));
    return r;
}
__device__ __forceinline__ float2 unpack2(unsigned long long v) {
    float2 f;
    asm("mov.b64 {%0, %1}, %2;" : "=f"(f.x), "=f"(f.y) : "l"(v));
    return f;
}
__device__ __forceinline__ unsigned ld_acquire(const unsigned* p) {
    unsigned v;
    asm volatile("ld.acquire.gpu.global.b32 %0, [%1];" : "=r"(v) : "l"(p));
    return v;
}
__device__ __forceinline__ void cp16(float* smem_dst, const float* gsrc) {
    unsigned d = (unsigned)__cvta_generic_to_shared(smem_dst);
    asm volatile("cp.async.ca.shared.global [%0], [%1], 16;" :: "r"(d), "l"(gsrc));
}

// ---------------- Phase 1: xW = x @ Wi + B, output TRANSPOSED [t][col][b] ----
// Block (0,0) additionally zeroes h buffer 0 and the flags (init fold-in:
// keeps the graph at 2 launches/replay so ncu -s 5 lands on the rec kernel).
__global__ void __launch_bounds__(256, 2)
xw_gemm_kernel(const float* __restrict__ x, const float* __restrict__ Wi,
               const float* __restrict__ bias) {
    __shared__ __align__(16) float As[2][8][132];
    __shared__ __align__(16) float Bs[3][8][128];

    const int tid = threadIdx.x;
    if (blockIdx.x == 0 && blockIdx.y == 0) {
        float4 z4 = make_float4(0.f, 0.f, 0.f, 0.f);
        #pragma unroll
        for (int i = 0; i < 32; i++)
            reinterpret_cast<float4*>(g_h)[tid + (i << 8)] = z4;   // 32768 floats
        if (tid < 128) g_flag[tid * 32] = 0u;
    }

    const int tx = tid & 15, ty = tid >> 4;
    const int bm = blockIdx.y << 7, bn = blockIdx.x << 7;
    const int lrow = tid >> 1, lk = (tid & 1) << 2;
    const int brow = tid >> 5, bcol = (tid & 31) << 2;

    unsigned long long acc2[8][4];
    #pragma unroll
    for (int i = 0; i < 8; i++)
        #pragma unroll
        for (int j = 0; j < 4; j++) acc2[i][j] = 0ull;

    const float* xrow = x + (size_t)(bm + lrow) * NI + lk;
    float4 av = *reinterpret_cast<const float4*>(xrow);
    cp16(&Bs[0][brow][bcol], Wi + (size_t)brow * NG + bn + bcol);
    asm volatile("cp.async.commit_group;");

    for (int i = 0; i < 32; i++) {
        const int cur = i & 1;
        As[cur][lk + 0][lrow] = av.x;
        As[cur][lk + 1][lrow] = av.y;
        As[cur][lk + 2][lrow] = av.z;
        As[cur][lk + 3][lrow] = av.w;
        if (i < 31) {
            av = *reinterpret_cast<const float4*>(xrow + (i + 1) * 8);
            cp16(&Bs[(i + 1) % 3][brow][bcol],
                 Wi + (size_t)((i + 1) * 8 + brow) * NG + bn + bcol);
            asm volatile("cp.async.commit_group;");
            asm volatile("cp.async.wait_group 1;");
        } else {
            asm volatile("cp.async.wait_group 0;");
        }
        __syncthreads();

        const float (*Ac)[132] = As[cur];
        const float (*Bc)[128] = Bs[i % 3];
        #pragma unroll
        for (int kk = 0; kk < 8; kk++) {
            float4 t0 = *reinterpret_cast<const float4*>(&Ac[kk][ty << 3]);
            float4 t1 = *reinterpret_cast<const float4*>(&Ac[kk][(ty << 3) + 4]);
            const ulonglong2* brow2 = reinterpret_cast<const ulonglong2*>(&Bc[kk][tx << 3]);
            ulonglong2 bv0 = brow2[0], bv1 = brow2[1];
            unsigned long long b2[4] = {bv0.x, bv0.y, bv1.x, bv1.y};
            float a[8] = {t0.x, t0.y, t0.z, t0.w, t1.x, t1.y, t1.z, t1.w};
            #pragma unroll
            for (int ii = 0; ii < 8; ii++) {
                unsigned long long ap = pack2(a[ii], a[ii]);
                #pragma unroll
                for (int j = 0; j < 4; j++)
                    acc2[ii][j] = fma2(ap, b2[j], acc2[ii][j]);
            }
        }
    }

    float4 bb0 = *reinterpret_cast<const float4*>(bias + bn + (tx << 3));
    float4 bb1 = *reinterpret_cast<const float4*>(bias + bn + (tx << 3) + 4);
    const float bb[8] = {bb0.x, bb0.y, bb0.z, bb0.w, bb1.x, bb1.y, bb1.z, bb1.w};

    const int t_idx = (bm >> 6) + (ty >> 3);
    const int b_base = (ty & 7) << 3;
    float o[8][8];
    #pragma unroll
    for (int i = 0; i < 8; i++)
        #pragma unroll
        for (int p = 0; p < 4; p++) {
            float2 v = unpack2(acc2[i][p]);
            o[i][2 * p] = v.x + bb[2 * p];
            o[i][2 * p + 1] = v.y + bb[2 * p + 1];
        }
    #pragma unroll
    for (int j = 0; j < 8; j++) {
        int col = bn + (tx << 3) + j;
        float* dst = g_xw + ((size_t)t_idx * NG + col) * NB + b_base;
        *reinterpret_cast<float4*>(dst)     = make_float4(o[0][j], o[1][j], o[2][j], o[3][j]);
        *reinterpret_cast<float4*>(dst + 4) = make_float4(o[4][j], o[5][j], o[6][j], o[7][j]);
    }
}

// ---------------- Phase 2: persistent recurrence (R6 structure + tail cuts) ----
// CTA (ug, bgp): units 16ug..+15 (64 gate cols), batches 16bgp..+15.
// 16 warps; warp w owns k rows [32w, 32w+32) in two 16-row chunks with separate
// producer flags: wait A -> stage A -> matmul A || wait B hidden -> stage B ->
// matmul B. Partials sRed[w][g][b16][u16]; one sync; 256 cell threads direct-
// reduce + cell + h store + bar9 + publish; out stores after publish.
// SMEM: sWh [512][64] 128KB | shT [512][16] 32KB | sRed [16][1024] 64KB = 224KB.
#define SMEM2_FLOATS (NH * 64 + NH * 16 + 16 * 1024)

__global__ void __launch_bounds__(512, 1)
lstm_rec_kernel(const float* __restrict__ Wh, float* __restrict__ out, int write_state) {
    extern __shared__ float smem[];
    float* sWh  = smem;                 // [k][64], c = gt*16+u16
    float* shT  = sWh + NH * 64;        // [k][16 batches]
    float* sRed = shT + NH * 16;        // [w][g][b16][u16]

    const int tid = threadIdx.x;
    const int wid = tid >> 5;
    const int lane = tid & 31;
    const int ug = blockIdx.x >> 2;
    const int bgp = blockIdx.x & 3;

    // Load Wh slice once: c = gt*16+u16 -> global col gt*512 + ug*16 + u16.
    for (int idx = tid; idx < NH * 64; idx += 512) {
        int k = idx >> 6, c = idx & 63;
        int gcol = ((c >> 4) << 9) + (ug << 4) + (c & 15);
        sWh[idx] = Wh[(size_t)k * NG + gcol];
    }
    __syncthreads();

    const int cg = lane >> 2, bq = lane & 3;
    const int g_of = cg >> 1, u8 = (cg & 1) << 3;
    const int srow = lane >> 2, spart = lane & 3;   // staging: row-in-8, quad

    const unsigned* fl0 = &g_flag[(bgp * 32 + 2 * wid) * 32];
    const unsigned* fl1 = &g_flag[(bgp * 32 + 2 * wid + 1) * 32];
    const unsigned* flown = &g_flag[(bgp * 32 + ug) * 32];

    const float* wbase = sWh + (wid << 5) * 64 + (cg << 3);
    const float* hbase = shT + (wid << 5) * 16 + (bq << 2);

    const int u_ = tid & 15, b2 = tid >> 4;         // cell mapping (tid<256)
    const int hrow = (ug << 4) + u_;
    const int bglob = (bgp << 4) + b2;
    float c_reg = 0.f;

    for (int t = 0; t < NT; t++) {
        // Prefetch xW (cell threads; streaming, in flight through the matmul).
        float xw0 = 0.f, xw1 = 0.f, xw2 = 0.f, xw3 = 0.f;
        if (tid < 256) {
            const float* xwt = g_xw + (size_t)t * ((size_t)NG * NB) + (size_t)hrow * NB + bglob;
            xw0 = __ldcs(xwt);
            xw1 = __ldcs(xwt + (size_t)(1 << 9) * NB);
            xw2 = __ldcs(xwt + (size_t)(2 << 9) * NB);
            xw3 = __ldcs(xwt + (size_t)(3 << 9) * NB);
        }

        const float* src = g_h + (t & 1) * (NH * NB) + (bgp << 4) + (spart << 2);
        unsigned long long acc[4][4];
        #pragma unroll
        for (int cp = 0; cp < 4; cp++)
            #pragma unroll
            for (int j = 0; j < 4; j++) acc[cp][j] = 0ull;

        #pragma unroll
        for (int ch = 0; ch < 2; ch++) {
            // Wait this chunk's producer flag (chunk B's wait hides behind matmul A).
            const unsigned* fl = ch ? fl1 : fl0;
            while (ld_acquire(fl) < (unsigned)t) { __nanosleep(20); }

            // Stage 16 rows x 16 floats with all 32 lanes (2 float4 each).
            const int rbase = (wid << 5) + (ch << 4);
            {
                int r0 = rbase + srow, r1 = rbase + 8 + srow;
                float4 v0 = __ldcg(reinterpret_cast<const float4*>(src + r0 * NB));
                float4 v1 = __ldcg(reinterpret_cast<const float4*>(src + r1 * NB));
                *reinterpret_cast<float4*>(shT + r0 * 16 + (spart << 2)) = v0;
                *reinterpret_cast<float4*>(shT + r1 * 16 + (spart << 2)) = v1;
            }
            __syncwarp();

            // Matmul over this 16-k chunk: 8 cols x 4 batches per lane.
            const float* wp_ = wbase + (ch << 4) * 64;
            const float* hp_ = hbase + (ch << 4) * 16;
            #pragma unroll 8
            for (int kl = 0; kl < 16; kl++) {
                ulonglong2 wA = *reinterpret_cast<const ulonglong2*>(wp_);
                ulonglong2 wB = *reinterpret_cast<const ulonglong2*>(wp_ + 4);
                float4 h = *reinterpret_cast<const float4*>(hp_);
                unsigned long long wq[4] = {wA.x, wA.y, wB.x, wB.y};
                unsigned long long hd[4] = {pack2(h.x, h.x), pack2(h.y, h.y),
                                            pack2(h.z, h.z), pack2(h.w, h.w)};
                #pragma unroll
                for (int cp = 0; cp < 4; cp++) {
                    acc[cp][0] = fma2(wq[cp], hd[0], acc[cp][0]);
                    acc[cp][1] = fma2(wq[cp], hd[1], acc[cp][1]);
                    acc[cp][2] = fma2(wq[cp], hd[2], acc[cp][2]);
                    acc[cp][3] = fma2(wq[cp], hd[3], acc[cp][3]);
                }
                wp_ += 64;
                hp_ += 16;
            }
            // __syncwarp not needed between chunks: staging writes of chunk B
            // touch different shT rows than chunk A reads.
        }

        // Partials: sRed[w][g][b16][u16].
        #pragma unroll
        for (int j = 0; j < 4; j++) {
            float2 p0 = unpack2(acc[0][j]);
            float2 p1 = unpack2(acc[1][j]);
            float2 p2 = unpack2(acc[2][j]);
            float2 p3 = unpack2(acc[3][j]);
            float* dst = sRed + (wid << 10) + (g_of << 8) + (((bq << 2) + j) << 4) + u8;
            *reinterpret_cast<float4*>(dst)     = make_float4(p0.x, p0.y, p1.x, p1.y);
            *reinterpret_cast<float4*>(dst + 4) = make_float4(p2.x, p2.y, p3.x, p3.y);
        }
        __syncthreads();   // partials visible to cell threads

        // Cell: direct 16-warp reduce + activations + h store (tid < 256).
        if (tid < 256) {
            float G0 = xw0, G1 = xw1, G2 = xw2, G3 = xw3;
            const float* rp = sRed + (b2 << 4) + u_;
            #pragma unroll
            for (int w = 0; w < 16; w++) {
                G0 += rp[0];
                G1 += rp[256];
                G2 += rp[512];
                G3 += rp[768];
                rp += 1024;
            }
            float ig = fast_sigmoid(G0);
            float fg = fast_sigmoid(G1);
            float gg = fast_tanh(G2);
            float og = fast_sigmoid(G3);
            c_reg = fg * c_reg + ig * gg;
            float h = og * fast_tanh(c_reg);

            __stcg(&g_h[((t + 1) & 1) * (NH * NB) + hrow * NB + bglob], h);
            asm volatile("bar.sync 9, 256;");   // all 256 cell h-stores issued
            if (tid == 0) {
                __threadfence();
                asm volatile("st.release.gpu.global.b32 [%0], %1;"
                             :: "l"(flown), "r"((unsigned)(t + 1)) : "memory");
            }
            // Off the critical path:
            __stcs(&out[((size_t)t * NB + bglob) * NH + hrow], h);
            if (write_state && t == NT - 1) {
                size_t base = (size_t)NT * NB * NH;
                out[base + (size_t)bglob * NH + hrow] = h;
                out[base + (size_t)NB * NH + (size_t)bglob * NH + hrow] = c_reg;
            }
        }
        __syncthreads();   // cell done: safe to restage shT / rewrite sRed next step
    }
}

extern "C" void kernel_launch(void* const* d_in, const int* in_sizes, int n_in,
                              void* d_out, int out_size) {
    const float* x  = (const float*)d_in[0];
    const float* Wi = (const float*)d_in[1];
    const float* Wh = (const float*)d_in[2];
    const float* B  = (const float*)d_in[3];
    float* out = (float*)d_out;

    const int smem_bytes = SMEM2_FLOATS * (int)sizeof(float);   // 229376 B
    cudaFuncSetAttribute(lstm_rec_kernel, cudaFuncAttributeMaxDynamicSharedMemorySize, smem_bytes);

    dim3 gA(NG / 128, (NT * NB) / 128);
    xw_gemm_kernel<<<gA, 256>>>(x, Wi, B);   // also zeroes h0 + flags (block 0,0)

    const long long need_full = (long long)NT * NB * NH + 2LL * NB * NH;
    int write_state = ((long long)out_size >= need_full) ? 1 : 0;

    lstm_rec_kernel<<<GRID_B, 512, smem_bytes>>>(Wh, out, write_state);
}

// round 12
// speedup vs baseline: 1.4165x; 1.1294x over previous
#include <cuda_runtime.h>
#include <cuda_bf16.h>
#include <math.h>
#include <stdint.h>

// Problem dims (fixed)
#define NT 2048
#define NB 64
#define NI 256
#define NH 512
#define NG 2048
#define GRID_B 128   // 32 unit-groups x 4 batch-groups, 1 CTA/SM, single wave

// Scratch (__device__ globals; no allocation allowed)
__device__ float g_xw[(size_t)NT * NG * NB];     // [t][col][b]
__device__ float g_h[2 * NH * NB];               // [buf][k][b]
__device__ unsigned g_flag[4 * 32 * 32];         // flag[(bgp*32+slice)*32] = step avail
__device__ uint4 g_xpack[(size_t)(NT * NB) * 64]; // 134MB: x split-bf16, frag-packed
__device__ uint4 g_wpack[(size_t)NG * 64];        // 2MB: Wi split-bf16, frag-packed

__device__ __forceinline__ float fast_sigmoid(float x) {
    return __fdividef(1.0f, 1.0f + __expf(-x));
}
__device__ __forceinline__ float fast_tanh(float x) {
    float t = __expf(2.0f * x);
    return 1.0f - __fdividef(2.0f, t + 1.0f);
}
__device__ __forceinline__ unsigned ld_acquire(const unsigned* p) {
    unsigned v;
    asm volatile("ld.acquire.gpu.global.b32 %0, [%1];" : "=r"(v) : "l"(p));
    return v;
}
__device__ __forceinline__ void cp16b(void* smem_dst, const void* gsrc) {
    unsigned d = (unsigned)__cvta_generic_to_shared(smem_dst);
    asm volatile("cp.async.ca.shared.global [%0], [%1], 16;" :: "r"(d), "l"(gsrc));
}

// pack (f_even, f_odd) -> u32 bf16x2, even in LOW half (PTX: second src -> low)
__device__ __forceinline__ unsigned bfpk(float f_even, float f_odd) {
    unsigned r;
    asm("cvt.rn.bf16x2.f32 %0, %1, %2;" : "=r"(r) : "f"(f_odd), "f"(f_even));
    return r;
}
// unpack bf16x2 halves to floats
__device__ __forceinline__ float bflo(unsigned p) { return __uint_as_float(p << 16); }
__device__ __forceinline__ float bfhi(unsigned p) { return __uint_as_float(p & 0xFFFF0000u); }

// entry = (hiPack(f0,f1), hiPack(f2,f3), loPack(f0,f1), loPack(f2,f3))
__device__ __forceinline__ uint4 split4(float f0, float f1, float f2, float f3) {
    uint4 r;
    r.x = bfpk(f0, f1);
    r.y = bfpk(f2, f3);
    r.z = bfpk(f0 - bflo(r.x), f1 - bfhi(r.x));
    r.w = bfpk(f2 - bflo(r.y), f3 - bfhi(r.y));
    return r;
}

__device__ __forceinline__ void mma_bf16(float* d, unsigned a0, unsigned a1,
                                         unsigned a2, unsigned a3,
                                         unsigned b0, unsigned b1) {
    asm volatile(
        "mma.sync.aligned.m16n8k16.row.col.f32.bf16.bf16.f32 "
        "{%0,%1,%2,%3}, {%4,%5,%6,%7}, {%8,%9}, {%0,%1,%2,%3};"
        : "+f"(d[0]), "+f"(d[1]), "+f"(d[2]), "+f"(d[3])
        : "r"(a0), "r"(a1), "r"(a2), "r"(a3), "r"(b0), "r"(b1));
}

// ---------------- Phase 0: pack x and Wi into mma fragment layouts ----------------
// x entry (m, e): e = ks*4+t -> k0 = 16ks+2t; words cover k0,k0+1 and k0+8,k0+9.
// Wi entry (n, e): same k pattern down column n.
// Grid 32768 x 256. Blocks 0..511 also pack Wi; block 1000 zeroes h0 + flags.
__global__ void __launch_bounds__(256)
pack_kernel(const float* __restrict__ x, const float* __restrict__ Wi) {
    const int tid = threadIdx.x;
    size_t id = (size_t)blockIdx.x * 256 + tid;

    {   // x pack (coalesced-ish float2 reads, coalesced uint4 writes)
        int m = (int)(id >> 6), e = (int)(id & 63);
        int k0 = ((e >> 2) << 4) + ((e & 3) << 1);
        const float* xr = x + (size_t)m * NI;
        float2 p0 = *reinterpret_cast<const float2*>(xr + k0);
        float2 p1 = *reinterpret_cast<const float2*>(xr + k0 + 8);
        g_xpack[id] = split4(p0.x, p0.y, p1.x, p1.y);
    }
    if (blockIdx.x < 512) {   // Wi pack: lanes sweep n (coalesced reads)
        int wi = blockIdx.x * 256 + tid;       // 0..131071
        int e = wi >> 11, n = wi & 2047;
        int k0 = ((e >> 2) << 4) + ((e & 3) << 1);
        float b00 = Wi[(size_t)k0 * NG + n];
        float b01 = Wi[(size_t)(k0 + 1) * NG + n];
        float b10 = Wi[(size_t)(k0 + 8) * NG + n];
        float b11 = Wi[(size_t)(k0 + 9) * NG + n];
        g_wpack[(size_t)n * 64 + e] = split4(b00, b01, b10, b11);
    }
    if (blockIdx.x == 1000) {   // init h0 + flags (every launch/replay)
        float4 z4 = make_float4(0.f, 0.f, 0.f, 0.f);
        #pragma unroll
        for (int i = 0; i < 32; i++)
            reinterpret_cast<float4*>(g_h)[tid + (i << 8)] = z4;
        if (tid < 128) g_flag[tid * 32] = 0u;
    }
}

// ---------------- Phase 1: xW = x @ Wi + B via split-bf16 mma.sync ----------------
// Tile 128x128, K=256 in 4 chunks of 64. 8 warps: warp (wm 0..3, wn 0..1) owns
// m32 x n64 (2 mtiles x 8 ntiles). 3 products: hi.hi + hi.lo + lo.hi.
// SMEM pitch 20 uint4/row -> all fragment LDS.128 verifed conflict-free.
#define PE 20
#define GEMM_SMEM (2 * 128 * PE * 16)   // 81920 B

__global__ void __launch_bounds__(256, 2)
xw_mma_kernel(const float* __restrict__ bias) {
    extern __shared__ uint4 smem4[];
    uint4* aS = smem4;                 // [128][PE]
    uint4* bS = smem4 + 128 * PE;      // [128][PE]

    const int tid = threadIdx.x;
    const int wid = tid >> 5, lane = tid & 31;
    const int g = lane >> 2, t = lane & 3;
    const int wm = wid >> 1, wn = wid & 1;
    const int bn = blockIdx.x << 7, bm = blockIdx.y << 7;

    float d[2][8][4];
    #pragma unroll
    for (int mt = 0; mt < 2; mt++)
        #pragma unroll
        for (int nt = 0; nt < 8; nt++)
            #pragma unroll
            for (int i = 0; i < 4; i++) d[mt][nt][i] = 0.f;

    for (int c = 0; c < 4; c++) {
        // Load chunk: 2048 entries A + 2048 entries B, 16 cp.async per thread.
        #pragma unroll
        for (int j = tid; j < 2048; j += 256) {
            int row = j >> 4, el = j & 15;
            cp16b(aS + row * PE + el, &g_xpack[(size_t)(bm + row) * 64 + c * 16 + el]);
            cp16b(bS + row * PE + el, &g_wpack[(size_t)(bn + row) * 64 + c * 16 + el]);
        }
        asm volatile("cp.async.commit_group;");
        asm volatile("cp.async.wait_group 0;");
        __syncthreads();

        #pragma unroll
        for (int ks = 0; ks < 4; ks++) {
            // A fragments: rows (g, g+8) of both mtiles.
            uint4 a0r0 = aS[(wm * 32 + g) * PE + ks * 4 + t];        // a0h,a2h,a0l,a2l
            uint4 a0r8 = aS[(wm * 32 + g + 8) * PE + ks * 4 + t];    // a1h,a3h,a1l,a3l
            uint4 a1r0 = aS[(wm * 32 + 16 + g) * PE + ks * 4 + t];
            uint4 a1r8 = aS[(wm * 32 + 24 + g) * PE + ks * 4 + t];
            #pragma unroll
            for (int nt = 0; nt < 8; nt++) {
                uint4 b = bS[(wn * 64 + nt * 8 + g) * PE + ks * 4 + t]; // b0h,b1h,b0l,b1l
                // mtile 0
                mma_bf16(d[0][nt], a0r0.x, a0r8.x, a0r0.y, a0r8.y, b.x, b.y); // hi.hi
                mma_bf16(d[0][nt], a0r0.x, a0r8.x, a0r0.y, a0r8.y, b.z, b.w); // hi.lo
                mma_bf16(d[0][nt], a0r0.z, a0r8.z, a0r0.w, a0r8.w, b.x, b.y); // lo.hi
                // mtile 1
                mma_bf16(d[1][nt], a1r0.x, a1r8.x, a1r0.y, a1r8.y, b.x, b.y);
                mma_bf16(d[1][nt], a1r0.x, a1r8.x, a1r0.y, a1r8.y, b.z, b.w);
                mma_bf16(d[1][nt], a1r0.z, a1r8.z, a1r0.w, a1r8.w, b.x, b.y);
            }
        }
        __syncthreads();
    }

    // Epilogue: add bias, store transposed g_xw[t][col][b].
    #pragma unroll
    for (int nt = 0; nt < 8; nt++) {
        int c0 = bn + wn * 64 + nt * 8 + 2 * t;
        float bb0 = bias[c0], bb1 = bias[c0 + 1];
        #pragma unroll
        for (int mt = 0; mt < 2; mt++) {
            int r0 = bm + wm * 32 + mt * 16 + g;
            int r1 = r0 + 8;
            size_t a0 = ((size_t)(r0 >> 6) * NG + c0) * NB + (r0 & 63);
            size_t a1 = ((size_t)(r1 >> 6) * NG + c0) * NB + (r1 & 63);
            g_xw[a0]      = d[mt][nt][0] + bb0;
            g_xw[a0 + NB] = d[mt][nt][1] + bb1;
            g_xw[a1]      = d[mt][nt][2] + bb0;
            g_xw[a1 + NB] = d[mt][nt][3] + bb1;
        }
    }
}

// ---------------- Phase 2: persistent recurrence (EXACT R10 structure) ----------------
#define SMEM2_FLOATS (NH * 64 + NH * 16 + 16 * 1024)

__device__ __forceinline__ unsigned long long fma2(unsigned long long a,
                                                   unsigned long long b,
                                                   unsigned long long c) {
    unsigned long long d;
    asm("fma.rn.f32x2 %0, %1, %2, %3;" : "=l"(d) : "l"(a), "l"(b), "l"(c));
    return d;
}
__device__ __forceinline__ unsigned long long pack2(float x, float y) {
    unsigned long long r;
    asm("mov.b64 %0, {%1, %2};" : "=l"(r) : "f"(x), "f"(y));
    return r;
}
__device__ __forceinline__ float2 unpack2(unsigned long long v) {
    float2 f;
    asm("mov.b64 {%0, %1}, %2;" : "=f"(f.x), "=f"(f.y) : "l"(v));
    return f;
}

__global__ void __launch_bounds__(512, 1)
lstm_rec_kernel(const float* __restrict__ Wh, float* __restrict__ out, int write_state) {
    extern __shared__ float smem[];
    float* sWh  = smem;                 // [k][64], c = gt*16+u16
    float* shT  = sWh + NH * 64;        // [k][16 batches]
    float* sRed = shT + NH * 16;        // [w][g][b16][u16]

    const int tid = threadIdx.x;
    const int wid = tid >> 5;
    const int lane = tid & 31;
    const int ug = blockIdx.x >> 2;
    const int bgp = blockIdx.x & 3;

    for (int idx = tid; idx < NH * 64; idx += 512) {
        int k = idx >> 6, c = idx & 63;
        int gcol = ((c >> 4) << 9) + (ug << 4) + (c & 15);
        sWh[idx] = Wh[(size_t)k * NG + gcol];
    }
    __syncthreads();

    const int cg = lane >> 2, bq = lane & 3;
    const int g_of = cg >> 1, u8 = (cg & 1) << 3;
    const int srow = lane >> 2, spart = lane & 3;

    const unsigned* fl0 = &g_flag[(bgp * 32 + 2 * wid) * 32];
    const unsigned* fl1 = &g_flag[(bgp * 32 + 2 * wid + 1) * 32];
    const unsigned* flown = &g_flag[(bgp * 32 + ug) * 32];

    const float* wbase = sWh + (wid << 5) * 64 + (cg << 3);
    const float* hbase = shT + (wid << 5) * 16 + (bq << 2);

    const int u_ = tid & 15, b2 = tid >> 4;
    const int hrow = (ug << 4) + u_;
    const int bglob = (bgp << 4) + b2;
    float c_reg = 0.f;

    for (int t = 0; t < NT; t++) {
        float xw0 = 0.f, xw1 = 0.f, xw2 = 0.f, xw3 = 0.f;
        if (tid < 256) {
            const float* xwt = g_xw + (size_t)t * ((size_t)NG * NB) + (size_t)hrow * NB + bglob;
            xw0 = __ldcs(xwt);
            xw1 = __ldcs(xwt + (size_t)(1 << 9) * NB);
            xw2 = __ldcs(xwt + (size_t)(2 << 9) * NB);
            xw3 = __ldcs(xwt + (size_t)(3 << 9) * NB);
        }

        const float* src = g_h + (t & 1) * (NH * NB) + (bgp << 4) + (spart << 2);
        unsigned long long acc[4][4];
        #pragma unroll
        for (int cp = 0; cp < 4; cp++)
            #pragma unroll
            for (int j = 0; j < 4; j++) acc[cp][j] = 0ull;

        #pragma unroll
        for (int ch = 0; ch < 2; ch++) {
            const unsigned* fl = ch ? fl1 : fl0;
            while (ld_acquire(fl) < (unsigned)t) { __nanosleep(20); }

            const int rbase = (wid << 5) + (ch << 4);
            {
                int r0 = rbase + srow, r1 = rbase + 8 + srow;
                float4 v0 = __ldcg(reinterpret_cast<const float4*>(src + r0 * NB));
                float4 v1 = __ldcg(reinterpret_cast<const float4*>(src + r1 * NB));
                *reinterpret_cast<float4*>(shT + r0 * 16 + (spart << 2)) = v0;
                *reinterpret_cast<float4*>(shT + r1 * 16 + (spart << 2)) = v1;
            }
            __syncwarp();

            const float* wp_ = wbase + (ch << 4) * 64;
            const float* hp_ = hbase + (ch << 4) * 16;
            #pragma unroll 8
            for (int kl = 0; kl < 16; kl++) {
                ulonglong2 wA = *reinterpret_cast<const ulonglong2*>(wp_);
                ulonglong2 wB = *reinterpret_cast<const ulonglong2*>(wp_ + 4);
                float4 h = *reinterpret_cast<const float4*>(hp_);
                unsigned long long wq[4] = {wA.x, wA.y, wB.x, wB.y};
                unsigned long long hd[4] = {pack2(h.x, h.x), pack2(h.y, h.y),
                                            pack2(h.z, h.z), pack2(h.w, h.w)};
                #pragma unroll
                for (int cp = 0; cp < 4; cp++) {
                    acc[cp][0] = fma2(wq[cp], hd[0], acc[cp][0]);
                    acc[cp][1] = fma2(wq[cp], hd[1], acc[cp][1]);
                    acc[cp][2] = fma2(wq[cp], hd[2], acc[cp][2]);
                    acc[cp][3] = fma2(wq[cp], hd[3], acc[cp][3]);
                }
                wp_ += 64;
                hp_ += 16;
            }
        }

        #pragma unroll
        for (int j = 0; j < 4; j++) {
            float2 p0 = unpack2(acc[0][j]);
            float2 p1 = unpack2(acc[1][j]);
            float2 p2 = unpack2(acc[2][j]);
            float2 p3 = unpack2(acc[3][j]);
            float* dst = sRed + (wid << 10) + (g_of << 8) + (((bq << 2) + j) << 4) + u8;
            *reinterpret_cast<float4*>(dst)     = make_float4(p0.x, p0.y, p1.x, p1.y);
            *reinterpret_cast<float4*>(dst + 4) = make_float4(p2.x, p2.y, p3.x, p3.y);
        }
        __syncthreads();

        if (tid < 256) {
            float G0 = xw0, G1 = xw1, G2 = xw2, G3 = xw3;
            const float* rp = sRed + (b2 << 4) + u_;
            #pragma unroll
            for (int w = 0; w < 16; w++) {
                G0 += rp[0];
                G1 += rp[256];
                G2 += rp[512];
                G3 += rp[768];
                rp += 1024;
            }
            float ig = fast_sigmoid(G0);
            float fg = fast_sigmoid(G1);
            float gg = fast_tanh(G2);
            float og = fast_sigmoid(G3);
            c_reg = fg * c_reg + ig * gg;
            float h = og * fast_tanh(c_reg);

            __stcg(&g_h[((t + 1) & 1) * (NH * NB) + hrow * NB + bglob], h);
            asm volatile("bar.sync 9, 256;");
            if (tid == 0) {
                __threadfence();
                asm volatile("st.release.gpu.global.b32 [%0], %1;"
                             :: "l"(flown), "r"((unsigned)(t + 1)) : "memory");
            }
            __stcs(&out[((size_t)t * NB + bglob) * NH + hrow], h);
            if (write_state && t == NT - 1) {
                size_t base = (size_t)NT * NB * NH;
                out[base + (size_t)bglob * NH + hrow] = h;
                out[base + (size_t)NB * NH + (size_t)bglob * NH + hrow] = c_reg;
            }
        }
        __syncthreads();
    }
}

extern "C" void kernel_launch(void* const* d_in, const int* in_sizes, int n_in,
                              void* d_out, int out_size) {
    const float* x  = (const float*)d_in[0];
    const float* Wi = (const float*)d_in[1];
    const float* Wh = (const float*)d_in[2];
    const float* B  = (const float*)d_in[3];
    float* out = (float*)d_out;

    cudaFuncSetAttribute(xw_mma_kernel, cudaFuncAttributeMaxDynamicSharedMemorySize,
                         GEMM_SMEM);
    const int smem2 = SMEM2_FLOATS * (int)sizeof(float);   // 229376 B
    cudaFuncSetAttribute(lstm_rec_kernel, cudaFuncAttributeMaxDynamicSharedMemorySize, smem2);

    // Phase 0: pack x + Wi to split-bf16 fragment layouts; init h0/flags.
    pack_kernel<<<(NT * NB * 64) / 256, 256>>>(x, Wi);

    // Phase 1: tensor-core GEMM.
    dim3 gA(NG / 128, (NT * NB) / 128);
    xw_mma_kernel<<<gA, 256, GEMM_SMEM>>>(B);

    const long long need_full = (long long)NT * NB * NH + 2LL * NB * NH;
    int write_state = ((long long)out_size >= need_full) ? 1 : 0;

    // Phase 2: persistent recurrence (R10).
    lstm_rec_kernel<<<GRID_B, 512, smem2>>>(Wh, out, write_state);
}